// round 11
// baseline (speedup 1.0000x reference)
#include <cuda_runtime.h>
#include <cuda_fp16.h>
#include <cstdint>

#define CIN 18
#define HH  256
#define WW  256
#define OCN 64
#define HWX 65536
#define NCHUNK 6          // 3 channels per 64-col chunk, 2 cols per tap

#define SMEM_A 0                     // 8 warps x 2 bufs x 8192 B = 131072
#define SMEM_B 131072                // 6 chunks x 8192 B = 49152
#define SMEM_TOTAL 180224

#define SW(o)  ((o) ^ (((o) >> 3) & 0x70))
// Extended swizzle for A: also fold row bit3 (offset bit10) into slot bit4 so
// the 2-rows-per-thread store phases are conflict-free (8 distinct slots).
#define SW2(o) ((o) ^ (((o) >> 3) & 0x70) ^ (((o) >> 6) & 0x10))

__device__ __forceinline__ uint32_t smem_u32(const void* p) {
    uint32_t a;
    asm("{ .reg .u64 t; cvta.to.shared.u64 t, %1; cvt.u32.u64 %0, t; }" : "=r"(a) : "l"(p));
    return a;
}
__device__ __forceinline__ void sts128(uint4 v, uint32_t addr) {
    asm volatile("st.shared.v4.b32 [%0], {%1, %2, %3, %4};"
                 :: "r"(addr), "r"(v.x), "r"(v.y), "r"(v.z), "r"(v.w) : "memory");
}
__device__ __forceinline__ void ldmatrix_x4(uint32_t* r, uint32_t addr) {
    asm volatile("ldmatrix.sync.aligned.m8n8.x4.shared.b16 {%0, %1, %2, %3}, [%4];"
                 : "=r"(r[0]), "=r"(r[1]), "=r"(r[2]), "=r"(r[3]) : "r"(addr));
}
__device__ __forceinline__ void mma16816(float* d, const uint32_t* a, const uint32_t* b) {
    asm volatile("mma.sync.aligned.m16n8k16.row.col.f32.f16.f16.f32 "
                 "{%0, %1, %2, %3}, {%4, %5, %6, %7}, {%8, %9}, {%0, %1, %2, %3};"
                 : "+f"(d[0]), "+f"(d[1]), "+f"(d[2]), "+f"(d[3])
                 : "r"(a[0]), "r"(a[1]), "r"(a[2]), "r"(a[3]), "r"(b[0]), "r"(b[1]));
}

// Load one tap row (4 x-positions) and immediately split to fp16 hi/lo.
__device__ __forceinline__ void load_row_h(const float* r, bool rv, bool lok, bool rok,
                                           __half* hh, __half* hl) {
    float f0 = 0.f, f1 = 0.f, f2 = 0.f, f3 = 0.f;
    if (rv) {
        if (lok) f0 = r[-1];
        float2 m = *reinterpret_cast<const float2*>(r);
        f1 = m.x; f2 = m.y;
        if (rok) f3 = r[2];
    }
    __half h0 = __float2half_rn(f0), h1 = __float2half_rn(f1),
           h2 = __float2half_rn(f2), h3 = __float2half_rn(f3);
    hh[0] = h0; hh[1] = h1; hh[2] = h2; hh[3] = h3;
    hl[0] = __float2half_rn(f0 - __half2float(h0));
    hl[1] = __float2half_rn(f1 - __half2float(h1));
    hl[2] = __float2half_rn(f2 - __half2float(h2));
    hl[3] = __float2half_rn(f3 - __half2float(h3));
}

__global__ __launch_bounds__(256)
void conv3x3_hmma6(const float* __restrict__ x,
                   const float* __restrict__ wgt,
                   const float* __restrict__ bias,
                   float* __restrict__ out) {
    extern __shared__ char smem[];
    const uint32_t sb   = smem_u32(smem);
    const int tid  = threadIdx.x;
    const int wid  = tid >> 5;
    const int lane = tid & 31;

    // ---- Build B once per CTA: chunk = 3 channels x 9 taps x (wh, wh) cols ----
    for (int i = tid; i < NCHUNK * 64; i += 256) {
        int chunk = i >> 6, oc = i & 63;
        __align__(16) __half cols[64];
        #pragma unroll
        for (int q = 0; q < 64; q++) cols[q] = __ushort_as_half(0);
        #pragma unroll
        for (int cl = 0; cl < 3; cl++) {
            int c = chunk * 3 + cl;
            #pragma unroll
            for (int t = 0; t < 9; t++) {
                __half h = __float2half_rn(wgt[oc * (CIN * 9) + c * 9 + t]);
                cols[cl * 18 + 2 * t + 0] = h;
                cols[cl * 18 + 2 * t + 1] = h;
            }
        }
        const uint4* src = reinterpret_cast<const uint4*>(cols);
        #pragma unroll
        for (int q = 0; q < 8; q++) {
            uint32_t off = (uint32_t)oc * 128 + q * 16;
            sts128(src[q], sb + SMEM_B + chunk * 8192 + SW(off));
        }
    }
    __syncthreads();   // B ready; the ONLY CTA barrier

    // Warp geometry: strip = 2 image rows x 256 px. Warp owns 64 px of one row.
    const int wy = wid >> 2;
    const int Xw = (wid & 3) * 64;
    const int x0 = Xw + 2 * lane;
    const uint32_t abase0 = sb + SMEM_A + (uint32_t)wid * 16384;

    const bool lok = (x0 > 0);
    const bool rok = (x0 + 2 < WW);
    const int tsel = lane >> 3, rr = lane & 7;
    const int r0 = 2 * lane, r1 = 2 * lane + 1;

    #pragma unroll 1
    for (int si = 0; si < 4; si++) {
        const int s = blockIdx.x * 4 + si;
        const int n = s >> 7;
        const int y = ((s & 127) << 1) + wy;
        const float* xs = x + (long)n * CIN * HWX;
        const bool t0 = (y > 0);
        const bool t2 = (y < HH - 1);

        __half hh[3][3][4], hl[3][3][4];
        // Prefetch + convert chunk-0 taps (channels 0..2).
        #pragma unroll
        for (int cl = 0; cl < 3; cl++) {
            const float* base = xs + (long)cl * HWX;
            #pragma unroll
            for (int ky = 0; ky < 3; ky++) {
                bool rv = (ky == 0) ? t0 : (ky == 2) ? t2 : true;
                load_row_h(base + (long)(y + ky - 1) * WW + x0, rv, lok, rok,
                           hh[cl][ky], hl[cl][ky]);
            }
        }

        float acc[4][8][4];
        #pragma unroll
        for (int mt = 0; mt < 4; mt++)
            #pragma unroll
            for (int nt = 0; nt < 8; nt++)
                #pragma unroll
                for (int qq = 0; qq < 4; qq++) acc[mt][nt][qq] = 0.0f;

        #pragma unroll 1
        for (int k = 0; k < NCHUNK; k++) {
            const uint32_t abuf = abase0 + (uint32_t)(k & 1) * 8192;

            // ---- Build A (2 px rows x 3 channels, (xh, xl) per tap) ----
            #pragma unroll
            for (int pxo = 0; pxo < 2; pxo++) {
                __align__(16) __half a[64];
                #pragma unroll
                for (int qq = 54; qq < 64; qq++) a[qq] = __ushort_as_half(0);
                #pragma unroll
                for (int cl = 0; cl < 3; cl++)
                    #pragma unroll
                    for (int ky = 0; ky < 3; ky++)
                        #pragma unroll
                        for (int kx = 0; kx < 3; kx++) {
                            int t = ky * 3 + kx;
                            a[cl * 18 + 2 * t + 0] = hh[cl][ky][kx + pxo];
                            a[cl * 18 + 2 * t + 1] = hl[cl][ky][kx + pxo];
                        }
                const uint4* src = reinterpret_cast<const uint4*>(a);
                uint32_t ro = (uint32_t)(pxo ? r1 : r0) * 128;
                #pragma unroll
                for (int qi = 0; qi < 8; qi++)
                    sts128(src[qi], abuf + SW2(ro + qi * 16));
            }
            __syncwarp();

            // Prefetch + convert next chunk's taps (LDGs fly under the MMAs).
            if (k + 1 < NCHUNK) {
                #pragma unroll
                for (int cl = 0; cl < 3; cl++) {
                    const float* base = xs + (long)((k + 1) * 3 + cl) * HWX;
                    #pragma unroll
                    for (int ky = 0; ky < 3; ky++) {
                        bool rv = (ky == 0) ? t0 : (ky == 2) ? t2 : true;
                        load_row_h(base + (long)(y + ky - 1) * WW + x0, rv, lok, rok,
                                   hh[cl][ky], hl[cl][ky]);
                    }
                }
            }

            // ---- MMA: warp tile 64 px x 64 oc, 4 k16 steps ----
            const uint32_t bb = sb + SMEM_B + k * 8192;
            #pragma unroll
            for (int st = 0; st < 4; st++) {
                uint32_t bfr[8][2];
                #pragma unroll
                for (int p = 0; p < 4; p++) {
                    int row = p * 16 + (tsel >> 1) * 8 + rr;
                    uint32_t off = (uint32_t)row * 128 + st * 32 + (tsel & 1) * 16;
                    uint32_t m[4];
                    ldmatrix_x4(m, bb + SW(off));
                    bfr[2 * p][0]     = m[0];
                    bfr[2 * p][1]     = m[1];
                    bfr[2 * p + 1][0] = m[2];
                    bfr[2 * p + 1][1] = m[3];
                }
                #pragma unroll
                for (int mt = 0; mt < 4; mt++) {
                    uint32_t afr[4];
                    int row = mt * 16 + (tsel & 1) * 8 + rr;
                    uint32_t off = (uint32_t)row * 128 + st * 32 + (tsel >> 1) * 16;
                    ldmatrix_x4(afr, abuf + SW2(off));
                    #pragma unroll
                    for (int nt = 0; nt < 8; nt++)
                        mma16816(acc[mt][nt], afr, bfr[nt]);
                }
            }
        }

        // ---- Epilogue: bias + store (warp's own 64 px of row y) ----
        float* ob = out + ((long)n * OCN) * HWX + (long)y * WW + Xw;
        #pragma unroll
        for (int nt = 0; nt < 8; nt++) {
            int oc0 = nt * 8 + (lane & 3) * 2;
            float b0 = bias[oc0], b1 = bias[oc0 + 1];
            float* p0 = ob + (long)oc0 * HWX;
            float* p1 = p0 + HWX;
            #pragma unroll
            for (int mt = 0; mt < 4; mt++) {
                int rl = mt * 16 + (lane >> 2);
                p0[rl]     = acc[mt][nt][0] + b0;
                p1[rl]     = acc[mt][nt][1] + b1;
                p0[rl + 8] = acc[mt][nt][2] + b0;
                p1[rl + 8] = acc[mt][nt][3] + b1;
            }
        }
    }
}

extern "C" void kernel_launch(void* const* d_in, const int* in_sizes, int n_in,
                              void* d_out, int out_size) {
    const float* x    = (const float*)d_in[0];
    const float* wgt  = (const float*)d_in[1];
    const float* bias = (const float*)d_in[2];
    float* out        = (float*)d_out;

    cudaFuncSetAttribute(conv3x3_hmma6, cudaFuncAttributeMaxDynamicSharedMemorySize, SMEM_TOTAL);
    conv3x3_hmma6<<<1024, 256, SMEM_TOTAL>>>(x, wgt, bias, out);
}

// round 12
// speedup vs baseline: 1.8869x; 1.8869x over previous
#include <cuda_runtime.h>
#include <cuda_fp16.h>
#include <cstdint>

#define CIN 18
#define HH  256
#define WW  256
#define OCN 64
#define HWX 65536
#define NCHUNK 6          // 3 channels x 9 taps = 27 cols (+5 pad) = 32 cols per chunk

#define SMEM_A 0                     // 8 warps x 2 blocks x 8192 B = 131072
#define SMEM_B 131072                // 3 blocks x 8192 B = 24576
#define SMEM_TOTAL 155648

#define SW(o)  ((o) ^ (((o) >> 3) & 0x70))

__device__ __forceinline__ uint32_t smem_u32(const void* p) {
    uint32_t a;
    asm("{ .reg .u64 t; cvta.to.shared.u64 t, %1; cvt.u32.u64 %0, t; }" : "=r"(a) : "l"(p));
    return a;
}
__device__ __forceinline__ void sts128(uint4 v, uint32_t addr) {
    asm volatile("st.shared.v4.b32 [%0], {%1, %2, %3, %4};"
                 :: "r"(addr), "r"(v.x), "r"(v.y), "r"(v.z), "r"(v.w) : "memory");
}
__device__ __forceinline__ void ldmatrix_x4(uint32_t* r, uint32_t addr) {
    asm volatile("ldmatrix.sync.aligned.m8n8.x4.shared.b16 {%0, %1, %2, %3}, [%4];"
                 : "=r"(r[0]), "=r"(r[1]), "=r"(r[2]), "=r"(r[3]) : "r"(addr));
}
__device__ __forceinline__ void mma16816(float* d, const uint32_t* a, const uint32_t* b) {
    asm volatile("mma.sync.aligned.m16n8k16.row.col.f32.f16.f16.f32 "
                 "{%0, %1, %2, %3}, {%4, %5, %6, %7}, {%8, %9}, {%0, %1, %2, %3};"
                 : "+f"(d[0]), "+f"(d[1]), "+f"(d[2]), "+f"(d[3])
                 : "r"(a[0]), "r"(a[1]), "r"(a[2]), "r"(a[3]), "r"(b[0]), "r"(b[1]));
}

__global__ __launch_bounds__(256)
void conv3x3_hmma7(const float* __restrict__ x,
                   const float* __restrict__ wgt,
                   const float* __restrict__ bias,
                   float* __restrict__ out) {
    extern __shared__ char smem[];
    const uint32_t sb   = smem_u32(smem);
    const int tid  = threadIdx.x;
    const int wid  = tid >> 5;
    const int lane = tid & 31;

    // ---- Build B once per CTA: chunk k -> block k>>1, column half (k&1)*64 B ----
    for (int i = tid; i < NCHUNK * 64; i += 256) {
        int chunk = i >> 6, oc = i & 63;
        __align__(16) __half cols[32];
        #pragma unroll
        for (int q = 27; q < 32; q++) cols[q] = __ushort_as_half(0);
        #pragma unroll
        for (int cl = 0; cl < 3; cl++) {
            int c = chunk * 3 + cl;
            #pragma unroll
            for (int t = 0; t < 9; t++)
                cols[cl * 9 + t] = __float2half_rn(wgt[oc * (CIN * 9) + c * 9 + t]);
        }
        const uint4* src = reinterpret_cast<const uint4*>(cols);
        uint32_t base = sb + SMEM_B + (chunk >> 1) * 8192;
        uint32_t co   = (chunk & 1) * 64;
        #pragma unroll
        for (int q = 0; q < 4; q++) {
            uint32_t off = (uint32_t)oc * 128 + co + q * 16;
            sts128(src[q], base + SW(off));
        }
    }
    __syncthreads();   // B ready; the ONLY CTA barrier

    // Warp geometry: strip = 2 image rows x 256 px. Warp owns 64 px of one row.
    const int wy = wid >> 2;
    const int Xw = (wid & 3) * 64;
    const int x0 = Xw + 2 * lane;
    const uint32_t abase0 = sb + SMEM_A + (uint32_t)wid * 16384;

    const bool lok = (x0 > 0);
    const bool rok = (x0 + 2 < WW);
    const int tsel = lane >> 3, rr = lane & 7;
    const int r0 = 2 * lane, r1 = 2 * lane + 1;

    #pragma unroll 1
    for (int si = 0; si < 4; si++) {
        const int s = blockIdx.x * 4 + si;
        const int n = s >> 7;
        const int y = ((s & 127) << 1) + wy;
        const float* xs = x + (long)n * CIN * HWX;
        const bool t0 = (y > 0);
        const bool t2 = (y < HH - 1);

        float q[3][3][4];
        // Prefetch chunk-0 taps (channels 0..2) into float regs.
        #pragma unroll
        for (int cl = 0; cl < 3; cl++) {
            const float* base = xs + (long)cl * HWX;
            #pragma unroll
            for (int ky = 0; ky < 3; ky++) {
                bool rv = (ky == 0) ? t0 : (ky == 2) ? t2 : true;
                const float* r = base + (long)(y + ky - 1) * WW + x0;
                if (rv) {
                    q[cl][ky][0] = lok ? r[-1] : 0.0f;
                    float2 m = *reinterpret_cast<const float2*>(r);
                    q[cl][ky][1] = m.x; q[cl][ky][2] = m.y;
                    q[cl][ky][3] = rok ? r[2] : 0.0f;
                } else {
                    q[cl][ky][0] = q[cl][ky][1] = q[cl][ky][2] = q[cl][ky][3] = 0.0f;
                }
            }
        }

        float acc[4][8][4];
        #pragma unroll
        for (int mt = 0; mt < 4; mt++)
            #pragma unroll
            for (int nt = 0; nt < 8; nt++)
                #pragma unroll
                for (int qq = 0; qq < 4; qq++) acc[mt][nt][qq] = 0.0f;

        #pragma unroll 1
        for (int k = 0; k < NCHUNK; k++) {
            const uint32_t abuf = abase0 + (uint32_t)((k >> 1) & 1) * 8192;
            const uint32_t co   = (uint32_t)(k & 1) * 64;

            // ---- Build A (2 px rows, 3 channels, 1 fp16 col per tap) ----
            __half hh[3][3][4];
            #pragma unroll
            for (int cl = 0; cl < 3; cl++)
                #pragma unroll
                for (int ky = 0; ky < 3; ky++)
                    #pragma unroll
                    for (int j = 0; j < 4; j++)
                        hh[cl][ky][j] = __float2half_rn(q[cl][ky][j]);
            #pragma unroll
            for (int pxo = 0; pxo < 2; pxo++) {
                __align__(16) __half a[32];
                #pragma unroll
                for (int qq = 27; qq < 32; qq++) a[qq] = __ushort_as_half(0);
                #pragma unroll
                for (int cl = 0; cl < 3; cl++)
                    #pragma unroll
                    for (int ky = 0; ky < 3; ky++)
                        #pragma unroll
                        for (int kx = 0; kx < 3; kx++)
                            a[cl * 9 + ky * 3 + kx] = hh[cl][ky][kx + pxo];
                const uint4* src = reinterpret_cast<const uint4*>(a);
                uint32_t ro = (uint32_t)(pxo ? r1 : r0) * 128 + co;
                #pragma unroll
                for (int qi = 0; qi < 4; qi++)
                    sts128(src[qi], abuf + SW(ro + qi * 16));
            }
            __syncwarp();

            // Prefetch next chunk's taps (LDGs fly under the MMAs).
            if (k + 1 < NCHUNK) {
                #pragma unroll
                for (int cl = 0; cl < 3; cl++) {
                    const float* base = xs + (long)((k + 1) * 3 + cl) * HWX;
                    #pragma unroll
                    for (int ky = 0; ky < 3; ky++) {
                        bool rv = (ky == 0) ? t0 : (ky == 2) ? t2 : true;
                        const float* r = base + (long)(y + ky - 1) * WW + x0;
                        if (rv) {
                            q[cl][ky][0] = lok ? r[-1] : 0.0f;
                            float2 m = *reinterpret_cast<const float2*>(r);
                            q[cl][ky][1] = m.x; q[cl][ky][2] = m.y;
                            q[cl][ky][3] = rok ? r[2] : 0.0f;
                        } else {
                            q[cl][ky][0] = q[cl][ky][1] = q[cl][ky][2] = q[cl][ky][3] = 0.0f;
                        }
                    }
                }
            }

            // ---- MMA: warp tile 64 px x 64 oc, 2 k16 steps ----
            const uint32_t bb = sb + SMEM_B + (k >> 1) * 8192;
            #pragma unroll
            for (int st = 0; st < 2; st++) {
                uint32_t bfr[8][2];
                #pragma unroll
                for (int p = 0; p < 4; p++) {
                    int row = p * 16 + (tsel >> 1) * 8 + rr;
                    uint32_t off = (uint32_t)row * 128 + co + st * 32 + (tsel & 1) * 16;
                    uint32_t m[4];
                    ldmatrix_x4(m, bb + SW(off));
                    bfr[2 * p][0]     = m[0];
                    bfr[2 * p][1]     = m[1];
                    bfr[2 * p + 1][0] = m[2];
                    bfr[2 * p + 1][1] = m[3];
                }
                #pragma unroll
                for (int mt = 0; mt < 4; mt++) {
                    uint32_t afr[4];
                    int row = mt * 16 + (tsel & 1) * 8 + rr;
                    uint32_t off = (uint32_t)row * 128 + co + st * 32 + (tsel >> 1) * 16;
                    ldmatrix_x4(afr, abuf + SW(off));
                    #pragma unroll
                    for (int nt = 0; nt < 8; nt++)
                        mma16816(acc[mt][nt], afr, bfr[nt]);
                }
            }
        }

        // ---- Epilogue: bias + store (warp's own 64 px of row y) ----
        float* ob = out + ((long)n * OCN) * HWX + (long)y * WW + Xw;
        #pragma unroll
        for (int nt = 0; nt < 8; nt++) {
            int oc0 = nt * 8 + (lane & 3) * 2;
            float b0 = bias[oc0], b1 = bias[oc0 + 1];
            float* p0 = ob + (long)oc0 * HWX;
            float* p1 = p0 + HWX;
            #pragma unroll
            for (int mt = 0; mt < 4; mt++) {
                int rl = mt * 16 + (lane >> 2);
                p0[rl]     = acc[mt][nt][0] + b0;
                p1[rl]     = acc[mt][nt][1] + b1;
                p0[rl + 8] = acc[mt][nt][2] + b0;
                p1[rl + 8] = acc[mt][nt][3] + b1;
            }
        }
    }
}

extern "C" void kernel_launch(void* const* d_in, const int* in_sizes, int n_in,
                              void* d_out, int out_size) {
    const float* x    = (const float*)d_in[0];
    const float* wgt  = (const float*)d_in[1];
    const float* bias = (const float*)d_in[2];
    float* out        = (float*)d_out;

    cudaFuncSetAttribute(conv3x3_hmma7, cudaFuncAttributeMaxDynamicSharedMemorySize, SMEM_TOTAL);
    conv3x3_hmma7<<<1024, 256, SMEM_TOTAL>>>(x, wgt, bias, out);
}

// round 14
// speedup vs baseline: 2.0383x; 1.0803x over previous
#include <cuda_runtime.h>
#include <cuda_fp16.h>
#include <cstdint>

#define CIN 18
#define HH  256
#define WW  256
#define OCN 64
#define HWX 65536
#define NCHUNK 6          // 3 channels x 9 taps = 27 cols (+5 pad) = 32 cols per chunk

#define SMEM_A 0                     // 8 warps x 2 blocks x 8192 B = 131072
#define SMEM_B 131072                // 3 blocks x 8192 B = 24576
#define SMEM_TOTAL 155648

#define SW(o)  ((o) ^ (((o) >> 3) & 0x70))

__device__ __forceinline__ uint32_t smem_u32(const void* p) {
    uint32_t a;
    asm("{ .reg .u64 t; cvta.to.shared.u64 t, %1; cvt.u32.u64 %0, t; }" : "=r"(a) : "l"(p));
    return a;
}
__device__ __forceinline__ void sts128(uint4 v, uint32_t addr) {
    asm volatile("st.shared.v4.b32 [%0], {%1, %2, %3, %4};"
                 :: "r"(addr), "r"(v.x), "r"(v.y), "r"(v.z), "r"(v.w) : "memory");
}
__device__ __forceinline__ void sts32f(float v, uint32_t addr) {
    asm volatile("st.shared.f32 [%0], %1;" :: "r"(addr), "f"(v) : "memory");
}
__device__ __forceinline__ float4 lds128f(uint32_t addr) {
    float4 v;
    asm volatile("ld.shared.v4.f32 {%0, %1, %2, %3}, [%4];"
                 : "=f"(v.x), "=f"(v.y), "=f"(v.z), "=f"(v.w) : "r"(addr));
    return v;
}
__device__ __forceinline__ void ldmatrix_x4(uint32_t* r, uint32_t addr) {
    asm volatile("ldmatrix.sync.aligned.m8n8.x4.shared.b16 {%0, %1, %2, %3}, [%4];"
                 : "=r"(r[0]), "=r"(r[1]), "=r"(r[2]), "=r"(r[3]) : "r"(addr));
}
__device__ __forceinline__ void mma16816(float* d, const uint32_t* a, const uint32_t* b) {
    asm volatile("mma.sync.aligned.m16n8k16.row.col.f32.f16.f16.f32 "
                 "{%0, %1, %2, %3}, {%4, %5, %6, %7}, {%8, %9}, {%0, %1, %2, %3};"
                 : "+f"(d[0]), "+f"(d[1]), "+f"(d[2]), "+f"(d[3])
                 : "r"(a[0]), "r"(a[1]), "r"(a[2]), "r"(a[3]), "r"(b[0]), "r"(b[1]));
}

__global__ __launch_bounds__(256)
void conv3x3_hmma8(const float* __restrict__ x,
                   const float* __restrict__ wgt,
                   const float* __restrict__ bias,
                   float* __restrict__ out) {
    extern __shared__ char smem[];
    const uint32_t sb   = smem_u32(smem);
    const int tid  = threadIdx.x;
    const int wid  = tid >> 5;
    const int lane = tid & 31;

    // ---- Build B once per CTA: chunk k -> block k>>1, column half (k&1)*64 B ----
    for (int i = tid; i < NCHUNK * 64; i += 256) {
        int chunk = i >> 6, oc = i & 63;
        __align__(16) __half cols[32];
        #pragma unroll
        for (int q = 27; q < 32; q++) cols[q] = __ushort_as_half(0);
        #pragma unroll
        for (int cl = 0; cl < 3; cl++) {
            int c = chunk * 3 + cl;
            #pragma unroll
            for (int t = 0; t < 9; t++)
                cols[cl * 9 + t] = __float2half_rn(wgt[oc * (CIN * 9) + c * 9 + t]);
        }
        const uint4* src = reinterpret_cast<const uint4*>(cols);
        uint32_t base = sb + SMEM_B + (chunk >> 1) * 8192;
        uint32_t co   = (chunk & 1) * 64;
        #pragma unroll
        for (int q = 0; q < 4; q++) {
            uint32_t off = (uint32_t)oc * 128 + co + q * 16;
            sts128(src[q], base + SW(off));
        }
    }
    __syncthreads();   // B ready; the ONLY CTA barrier

    // Warp geometry: strip = 2 image rows x 256 px. Warp owns 64 px of one row.
    const int wy = wid >> 2;
    const int Xw = (wid & 3) * 64;
    const int x0 = Xw + 2 * lane;
    const uint32_t abase0 = sb + SMEM_A + (uint32_t)wid * 16384;

    const bool lok = (x0 > 0);
    const bool rok = (x0 + 2 < WW);
    const int tsel = lane >> 3, rr = lane & 7;
    const int r0 = 2 * lane, r1 = 2 * lane + 1;

    #pragma unroll 1
    for (int si = 0; si < 4; si++) {
        const int s = blockIdx.x * 4 + si;
        const int n = s >> 7;
        const int y = ((s & 127) << 1) + wy;
        const float* xs = x + (long)n * CIN * HWX;
        const bool t0 = (y > 0);
        const bool t2 = (y < HH - 1);

        float q[3][3][4];
        // Prefetch chunk-0 taps (channels 0..2) into float regs.
        #pragma unroll
        for (int cl = 0; cl < 3; cl++) {
            const float* base = xs + (long)cl * HWX;
            #pragma unroll
            for (int ky = 0; ky < 3; ky++) {
                bool rv = (ky == 0) ? t0 : (ky == 2) ? t2 : true;
                const float* r = base + (long)(y + ky - 1) * WW + x0;
                if (rv) {
                    q[cl][ky][0] = lok ? r[-1] : 0.0f;
                    float2 m = *reinterpret_cast<const float2*>(r);
                    q[cl][ky][1] = m.x; q[cl][ky][2] = m.y;
                    q[cl][ky][3] = rok ? r[2] : 0.0f;
                } else {
                    q[cl][ky][0] = q[cl][ky][1] = q[cl][ky][2] = q[cl][ky][3] = 0.0f;
                }
            }
        }

        float acc[4][8][4];
        #pragma unroll
        for (int mt = 0; mt < 4; mt++)
            #pragma unroll
            for (int nt = 0; nt < 8; nt++)
                #pragma unroll
                for (int qq = 0; qq < 4; qq++) acc[mt][nt][qq] = 0.0f;

        #pragma unroll 1
        for (int k = 0; k < NCHUNK; k++) {
            const uint32_t abuf = abase0 + (uint32_t)((k >> 1) & 1) * 8192;
            const uint32_t co   = (uint32_t)(k & 1) * 64;

            // ---- Build A (2 px rows, 3 channels, 1 fp16 col per tap) ----
            __half hh[3][3][4];
            #pragma unroll
            for (int cl = 0; cl < 3; cl++)
                #pragma unroll
                for (int ky = 0; ky < 3; ky++)
                    #pragma unroll
                    for (int j = 0; j < 4; j++)
                        hh[cl][ky][j] = __float2half_rn(q[cl][ky][j]);
            #pragma unroll
            for (int pxo = 0; pxo < 2; pxo++) {
                __align__(16) __half a[32];
                #pragma unroll
                for (int qq = 27; qq < 32; qq++) a[qq] = __ushort_as_half(0);
                #pragma unroll
                for (int cl = 0; cl < 3; cl++)
                    #pragma unroll
                    for (int ky = 0; ky < 3; ky++)
                        #pragma unroll
                        for (int kx = 0; kx < 3; kx++)
                            a[cl * 9 + ky * 3 + kx] = hh[cl][ky][kx + pxo];
                const uint4* src = reinterpret_cast<const uint4*>(a);
                uint32_t ro = (uint32_t)(pxo ? r1 : r0) * 128 + co;
                #pragma unroll
                for (int qi = 0; qi < 4; qi++)
                    sts128(src[qi], abuf + SW(ro + qi * 16));
            }
            __syncwarp();

            // Prefetch next chunk's taps (LDGs fly under the MMAs).
            if (k + 1 < NCHUNK) {
                #pragma unroll
                for (int cl = 0; cl < 3; cl++) {
                    const float* base = xs + (long)((k + 1) * 3 + cl) * HWX;
                    #pragma unroll
                    for (int ky = 0; ky < 3; ky++) {
                        bool rv = (ky == 0) ? t0 : (ky == 2) ? t2 : true;
                        const float* r = base + (long)(y + ky - 1) * WW + x0;
                        if (rv) {
                            q[cl][ky][0] = lok ? r[-1] : 0.0f;
                            float2 m = *reinterpret_cast<const float2*>(r);
                            q[cl][ky][1] = m.x; q[cl][ky][2] = m.y;
                            q[cl][ky][3] = rok ? r[2] : 0.0f;
                        } else {
                            q[cl][ky][0] = q[cl][ky][1] = q[cl][ky][2] = q[cl][ky][3] = 0.0f;
                        }
                    }
                }
            }

            // ---- MMA: warp tile 64 px x 64 oc, 2 k16 steps ----
            const uint32_t bb = sb + SMEM_B + (k >> 1) * 8192;
            #pragma unroll
            for (int st = 0; st < 2; st++) {
                uint32_t bfr[8][2];
                #pragma unroll
                for (int p = 0; p < 4; p++) {
                    int row = p * 16 + (tsel >> 1) * 8 + rr;
                    uint32_t off = (uint32_t)row * 128 + co + st * 32 + (tsel & 1) * 16;
                    uint32_t m[4];
                    ldmatrix_x4(m, bb + SW(off));
                    bfr[2 * p][0]     = m[0];
                    bfr[2 * p][1]     = m[1];
                    bfr[2 * p + 1][0] = m[2];
                    bfr[2 * p + 1][1] = m[3];
                }
                #pragma unroll
                for (int mt = 0; mt < 4; mt++) {
                    uint32_t afr[4];
                    int row = mt * 16 + (tsel & 1) * 8 + rr;
                    uint32_t off = (uint32_t)row * 128 + co + st * 32 + (tsel >> 1) * 16;
                    ldmatrix_x4(afr, abuf + SW(off));
                    #pragma unroll
                    for (int nt = 0; nt < 8; nt++)
                        mma16816(acc[mt][nt], afr, bfr[nt]);
                }
            }
        }

        // ---- Epilogue: transpose through warp-private smem, coalesced STG.128 ----
        // 4 passes of 16 oc; tile [16 oc][68 f32-pad rows] = 4352 B in abase0.
        float* ob = out + ((long)n * OCN) * HWX + (long)y * WW + Xw;
        const uint32_t tb = abase0;
        #pragma unroll
        for (int pass = 0; pass < 4; pass++) {
            __syncwarp();   // previous pass's LDS done before overwrite
            #pragma unroll
            for (int t = 0; t < 2; t++) {
                const int nt  = pass * 2 + t;
                const int ocl = t * 8 + (lane & 3) * 2;       // oc within window
                const int ocg = pass * 16 + ocl;
                const float b0 = bias[ocg], b1 = bias[ocg + 1];
                const uint32_t a0 = tb + (uint32_t)ocl * 272;
                const uint32_t a1 = a0 + 272;
                #pragma unroll
                for (int mt = 0; mt < 4; mt++) {
                    const int rl = mt * 16 + (lane >> 2);
                    sts32f(acc[mt][nt][0] + b0, a0 + rl * 4);
                    sts32f(acc[mt][nt][1] + b1, a1 + rl * 4);
                    sts32f(acc[mt][nt][2] + b0, a0 + (rl + 8) * 4);
                    sts32f(acc[mt][nt][3] + b1, a1 + (rl + 8) * 4);
                }
            }
            __syncwarp();
            #pragma unroll
            for (int j = 0; j < 8; j++) {
                const int idx  = j * 32 + lane;
                const int ocl  = idx >> 4;        // 0..15
                const int quad = idx & 15;        // 16-B quad (4 px)
                float4 v = lds128f(tb + (uint32_t)ocl * 272 + quad * 16);
                float* p = ob + (long)(pass * 16 + ocl) * HWX + quad * 4;
                *reinterpret_cast<float4*>(p) = v;
            }
        }
        __syncwarp();   // epilogue reads done before next strip's A build
    }
}

extern "C" void kernel_launch(void* const* d_in, const int* in_sizes, int n_in,
                              void* d_out, int out_size) {
    const float* x    = (const float*)d_in[0];
    const float* wgt  = (const float*)d_in[1];
    const float* bias = (const float*)d_in[2];
    float* out        = (float*)d_out;

    cudaFuncSetAttribute(conv3x3_hmma8, cudaFuncAttributeMaxDynamicSharedMemorySize, SMEM_TOTAL);
    conv3x3_hmma8<<<1024, 256, SMEM_TOTAL>>>(x, wgt, bias, out);
}